// round 14
// baseline (speedup 1.0000x reference)
#include <cuda_runtime.h>
#include <cuda_bf16.h>

#define D      1024
#define BATCH  64
#define KV     4096
#define KV1    4097
#define NCHUNK 32

// Role ranges in the mega kernel (1D grid, in-order dispatch)
#define N_G0   1536                      // QKV gemm blocks
#define N_SC   (64 * 257)                // scores blocks
#define N_AT   (64 * NCHUNK)             // attn blocks
#define N_G1   512                       // out-proj gemm blocks
#define ID_SC  N_G0
#define ID_AT  (N_G0 + N_SC)
#define ID_G1  (N_G0 + N_SC + N_AT)
#define N_ALL  (N_G0 + N_SC + N_AT + N_G1)

// Scratch (no allocations allowed) ------------------------------------------
__device__ float g_cur[BATCH * D];
__device__ float g_q[BATCH * D];
__device__ float g_knew[BATCH * D];
__device__ float g_vnew[BATCH * D];
__device__ float g_scores[BATCH * KV1];   // exp(score), unnormalized
__device__ float g_attn[BATCH * D];
__device__ float g_sumexp[BATCH];
__device__ int   g_ready[BATCH * NCHUNK];
__device__ int   g_qkv_done;
__device__ int   g_attn_done;

// ---------------------------------------------------------------------------
// Launch 1: embedding gather, bias pre-init, and flag zeroing (per replay).
__global__ void init_kernel(const int* __restrict__ x, const float* __restrict__ emb,
                            const float* __restrict__ bq, const float* __restrict__ bk,
                            const float* __restrict__ bv, const float* __restrict__ bo,
                            float* __restrict__ out) {
    int b = blockIdx.x;
    int row = x[b];
    if (threadIdx.x < NCHUNK) g_ready[b * NCHUNK + threadIdx.x] = 0;
    if (threadIdx.x == 0) {
        g_sumexp[b] = 0.f;
        if (b == 0) { g_qkv_done = 0; g_attn_done = 0; }
    }
    for (int i = threadIdx.x; i < D; i += blockDim.x) {
        g_cur[b * D + i]  = emb[(size_t)row * D + i];
        g_q[b * D + i]    = bq[i];
        g_knew[b * D + i] = bk[i];
        g_vnew[b * D + i] = bv[i];
        g_attn[b * D + i] = 0.f;
        out[b * D + i]    = bo[i];
    }
}

// ---------------------------------------------------------------------------
// Launch 2: everything else, role by block id.
__global__ void __launch_bounds__(512)
mega_kernel(const float* __restrict__ prev_k, const float* __restrict__ prev_v,
            const float* __restrict__ Wq, const float* __restrict__ Wk,
            const float* __restrict__ Wv, const float* __restrict__ Wo,
            float* __restrict__ out,
            float* __restrict__ k_out, float* __restrict__ v_out) {
    const int id  = blockIdx.x;
    const int tid = threadIdx.x;
    const int wid = tid >> 5, lane = tid & 31;

    __shared__ union {
        float4 qs[D / 4];
        struct { float As[64][65]; float Ws[32][65]; } g;
    } sm;
    __shared__ float ps[132];

    if (id < ID_SC) {
        // ===================== QKV GEMM role =====================
        // 512 blocks per weight matrix: 32 e-tiles x 16 k-slices.
        const int z  = id / 512;
        const int r  = id % 512;
        const int e0 = (r & 31) * 32;
        const int k0 = (r >> 5) * 64;
        const float* W = (z == 0) ? Wq : (z == 1) ? Wk : Wv;
        float* C = (z == 0) ? g_q : (z == 1) ? g_knew : g_vnew;

        const int ty = tid >> 5;          // 0..15  -> 4 b-rows each
        const int tx = tid & 31;          // 0..31  -> 1 e-col each

        for (int i = tid; i < 1024; i += 512) {
            int rw = i >> 4, c4 = (i & 15) * 4;
            float4 a = *(const float4*)(g_cur + (size_t)rw * D + k0 + c4);
            sm.g.As[rw][c4 + 0] = a.x; sm.g.As[rw][c4 + 1] = a.y;
            sm.g.As[rw][c4 + 2] = a.z; sm.g.As[rw][c4 + 3] = a.w;
        }
        {
            int rw = tid >> 4, c4 = (tid & 15) * 4;
            float4 w = *(const float4*)(W + (size_t)(e0 + rw) * D + k0 + c4);
            sm.g.Ws[rw][c4 + 0] = w.x; sm.g.Ws[rw][c4 + 1] = w.y;
            sm.g.Ws[rw][c4 + 2] = w.z; sm.g.Ws[rw][c4 + 3] = w.w;
        }
        __syncthreads();
        float acc[4] = {};
        #pragma unroll
        for (int kk = 0; kk < 64; kk++) {
            float w = sm.g.Ws[tx][kk];
            #pragma unroll
            for (int i = 0; i < 4; i++) acc[i] += sm.g.As[ty * 4 + i][kk] * w;
        }
        #pragma unroll
        for (int i = 0; i < 4; i++)
            atomicAdd(&C[(size_t)(ty * 4 + i) * D + e0 + tx], acc[i]);
        __threadfence();
        __syncthreads();
        if (tid == 0) atomicAdd(&g_qkv_done, 1);

    } else if (id < ID_AT) {
        // ===================== scores role =====================
        const int id2 = id - ID_SC;
        const int y = id2 >> 6;           // 0..256  (y-major, matches R13)
        const int b = id2 & 63;

        if (tid == 0) {
            while (atomicAdd(&g_qkv_done, 0) < N_G0) __nanosleep(64);
        }
        __syncthreads();

        for (int i = tid; i < D / 4; i += 512)
            sm.qs[i] = ((const float4*)(g_q + b * D))[i];
        __syncthreads();

        int s = y * 16 + wid;
        float e = 0.f;
        if (s <= KV) {
            const float4* src = (s < KV)
                ? (const float4*)(prev_k + ((size_t)b * KV + s) * D)
                : (const float4*)(g_knew + b * D);
            float4* dst = (float4*)(k_out + ((size_t)b * KV1 + s) * D);

            float4 kv[8];
            #pragma unroll
            for (int i = 0; i < 8; i++) kv[i] = __ldcs(src + lane + i * 32);

            float acc = 0.f;
            #pragma unroll
            for (int i = 0; i < 8; i++) {
                float4 qv = sm.qs[lane + i * 32];
                acc += kv[i].x * qv.x + kv[i].y * qv.y + kv[i].z * qv.z + kv[i].w * qv.w;
                __stcs(dst + lane + i * 32, kv[i]);
            }
            #pragma unroll
            for (int o = 16; o; o >>= 1) acc += __shfl_xor_sync(0xffffffffu, acc, o);
            e = __expf(acc * 0.03125f);          // 1/sqrt(1024)
            if (lane == 0) g_scores[b * KV1 + s] = e;
        }
        if (lane == 0) { __threadfence(); ps[wid] = e; }
        __syncthreads();
        if (tid < 32) {
            float v = (tid < 16) ? ps[tid] : 0.f;
            #pragma unroll
            for (int o = 16; o; o >>= 1) v += __shfl_xor_sync(0xffffffffu, v, o);
            if (tid == 0) {
                atomicAdd(&g_sumexp[b], v);
                __threadfence();
                int chunk = y >> 3; if (chunk > 31) chunk = 31;
                atomicAdd(&g_ready[b * NCHUNK + chunk], 1);
            }
        }

    } else if (id < ID_G1) {
        // ===================== attn role =====================
        const int id3 = id - ID_AT;
        const int chunk = id3 >> 6;       // chunk-major, matches R13
        const int b = id3 & 63;
        const int s0 = chunk * 128;
        const bool last = (chunk == NCHUNK - 1);
        const int target = last ? 9 : 8;

        if (tid == 0) {
            while (atomicAdd(&g_ready[b * NCHUNK + chunk], 0) < target) __nanosleep(64);
        }
        __syncthreads();

        const float* p = g_scores + b * KV1;
        if (tid < 128) ps[tid] = p[s0 + tid];
        if (last && tid == 128) ps[128] = p[KV];
        __syncthreads();

        const int col = tid & 255;
        const int rbeg = (tid >> 8) * 64;
        const float4* vbase = (const float4*)(prev_v + (size_t)b * KV * D) + col;
        float4* obase = (float4*)(v_out + (size_t)b * KV1 * D) + col;

        float4 acc = make_float4(0.f, 0.f, 0.f, 0.f);
        for (int s = 0; s < 64; s += 8) {
            float4 val[8];
            #pragma unroll
            for (int j = 0; j < 8; j++)
                val[j] = __ldcs(vbase + (size_t)(s0 + rbeg + s + j) * (D / 4));
            #pragma unroll
            for (int j = 0; j < 8; j++) {
                float w = ps[rbeg + s + j];
                acc.x += w * val[j].x; acc.y += w * val[j].y;
                acc.z += w * val[j].z; acc.w += w * val[j].w;
                __stcs(obase + (size_t)(s0 + rbeg + s + j) * (D / 4), val[j]);
            }
        }
        if (last && rbeg == 0) {                 // new row s = 4096
            float4 val = ((const float4*)(g_vnew + b * D))[col];
            float w = ps[128];
            acc.x += w * val.x; acc.y += w * val.y;
            acc.z += w * val.z; acc.w += w * val.w;
            __stcs(obase + (size_t)KV * (D / 4), val);
        }
        float* ga = g_attn + b * D + col * 4;
        atomicAdd(ga + 0, acc.x);
        atomicAdd(ga + 1, acc.y);
        atomicAdd(ga + 2, acc.z);
        atomicAdd(ga + 3, acc.w);
        __threadfence();
        __syncthreads();
        if (tid == 0) atomicAdd(&g_attn_done, 1);

    } else {
        // ===================== out-projection GEMM role =====================
        const int id4 = id - ID_G1;
        const int e0 = (id4 & 31) * 32;
        const int k0 = (id4 >> 5) * 64;
        const int ty = tid >> 5;
        const int tx = tid & 31;

        if (tid == 0) {
            while (atomicAdd(&g_attn_done, 0) < N_AT) __nanosleep(128);
        }
        __syncthreads();

        for (int i = tid; i < 1024; i += 512) {
            int rw = i >> 4, c4 = (i & 15) * 4;
            float4 a = *(const float4*)(g_attn + (size_t)rw * D + k0 + c4);
            sm.g.As[rw][c4 + 0] = a.x; sm.g.As[rw][c4 + 1] = a.y;
            sm.g.As[rw][c4 + 2] = a.z; sm.g.As[rw][c4 + 3] = a.w;
        }
        {
            int rw = tid >> 4, c4 = (tid & 15) * 4;
            float4 w = *(const float4*)(Wo + (size_t)(e0 + rw) * D + k0 + c4);
            sm.g.Ws[rw][c4 + 0] = w.x; sm.g.Ws[rw][c4 + 1] = w.y;
            sm.g.Ws[rw][c4 + 2] = w.z; sm.g.Ws[rw][c4 + 3] = w.w;
        }
        __syncthreads();
        float acc[4] = {};
        #pragma unroll
        for (int kk = 0; kk < 64; kk++) {
            float w = sm.g.Ws[tx][kk];
            #pragma unroll
            for (int i = 0; i < 4; i++) acc[i] += sm.g.As[ty * 4 + i][kk] * w;
        }
        #pragma unroll
        for (int i = 0; i < 4; i++) {
            int b = ty * 4 + i;
            float scale = 1.0f / g_sumexp[b];
            atomicAdd(&out[(size_t)b * D + e0 + tx], acc[i] * scale);
        }
    }
}

// ---------------------------------------------------------------------------
extern "C" void kernel_launch(void* const* d_in, const int* in_sizes, int n_in,
                              void* d_out, int out_size) {
    const int*   x      = (const int*)d_in[0];
    const float* prev_k = (const float*)d_in[1];
    const float* prev_v = (const float*)d_in[2];
    const float* emb    = (const float*)d_in[3];
    const float* Wq     = (const float*)d_in[4];
    const float* bq     = (const float*)d_in[5];
    const float* Wk     = (const float*)d_in[6];
    const float* bk     = (const float*)d_in[7];
    const float* Wv     = (const float*)d_in[8];
    const float* bv     = (const float*)d_in[9];
    const float* Wo     = (const float*)d_in[10];
    const float* bo     = (const float*)d_in[11];

    float* out   = (float*)d_out;                       // (64, 1, 1024)
    float* k_out = out + (size_t)BATCH * D;             // (64, 4097, 1024)
    float* v_out = k_out + (size_t)BATCH * KV1 * D;     // (64, 4097, 1024)

    init_kernel<<<BATCH, 512>>>(x, emb, bq, bk, bv, bo, out);
    mega_kernel<<<N_ALL, 512>>>(prev_k, prev_v, Wq, Wk, Wv, Wo, out, k_out, v_out);
}

// round 15
// speedup vs baseline: 1.0033x; 1.0033x over previous
#include <cuda_runtime.h>
#include <cuda_bf16.h>

#define D      1024
#define BATCH  64
#define KV     4096
#define KV1    4097
#define NCHUNK 32
#define N_AT   (BATCH * NCHUNK)

// Scratch (no allocations allowed) ------------------------------------------
__device__ float g_cur[BATCH * D];
__device__ float g_q[BATCH * D];
__device__ float g_knew[BATCH * D];
__device__ float g_vnew[BATCH * D];
__device__ float g_scores[BATCH * KV1];   // exp(score), unnormalized
__device__ float g_attn[BATCH * D];
__device__ float g_sumexp[BATCH];
__device__ int   g_ready[BATCH * NCHUNK];
__device__ int   g_attn_done;

// ---------------------------------------------------------------------------
__global__ void init_kernel(const int* __restrict__ x, const float* __restrict__ emb,
                            const float* __restrict__ bq, const float* __restrict__ bk,
                            const float* __restrict__ bv, const float* __restrict__ bo,
                            float* __restrict__ out) {
    int b = blockIdx.x;
    int row = x[b];
    if (threadIdx.x < NCHUNK) g_ready[b * NCHUNK + threadIdx.x] = 0;
    if (threadIdx.x == 0) {
        g_sumexp[b] = 0.f;
        if (b == 0) g_attn_done = 0;
    }
    for (int i = threadIdx.x; i < D; i += blockDim.x) {
        g_cur[b * D + i]  = emb[(size_t)row * D + i];
        g_q[b * D + i]    = bq[i];
        g_knew[b * D + i] = bk[i];
        g_vnew[b * D + i] = bv[i];
        g_attn[b * D + i] = 0.f;
        out[b * D + i]    = bo[i];
    }
}

// ---------------------------------------------------------------------------
// QKV split-K GEMM (proven R12/R13 shape): grid (32,16,3), 256 threads.
__global__ void gemm_qkv(const float* __restrict__ Wq, const float* __restrict__ Wk,
                         const float* __restrict__ Wv) {
    const float* W = (blockIdx.z == 0) ? Wq : (blockIdx.z == 1) ? Wk : Wv;
    float* C = (blockIdx.z == 0) ? g_q : (blockIdx.z == 1) ? g_knew : g_vnew;

    __shared__ float As[64][65];
    __shared__ float Ws[32][65];
    const int e0 = blockIdx.x * 32;
    const int k0 = blockIdx.y * 64;
    const int tid = threadIdx.x;
    const int ty = tid >> 4, tx = tid & 15;
    float acc[4][2] = {};

    for (int i = tid; i < 1024; i += 256) {
        int row = i >> 4, c4 = (i & 15) * 4;
        float4 a = *(const float4*)(g_cur + (size_t)row * D + k0 + c4);
        As[row][c4 + 0] = a.x; As[row][c4 + 1] = a.y;
        As[row][c4 + 2] = a.z; As[row][c4 + 3] = a.w;
    }
    for (int i = tid; i < 512; i += 256) {
        int row = i >> 4, c4 = (i & 15) * 4;
        float4 w = *(const float4*)(W + (size_t)(e0 + row) * D + k0 + c4);
        Ws[row][c4 + 0] = w.x; Ws[row][c4 + 1] = w.y;
        Ws[row][c4 + 2] = w.z; Ws[row][c4 + 3] = w.w;
    }
    __syncthreads();
    #pragma unroll
    for (int kk = 0; kk < 64; kk++) {
        float av[4], wv[2];
        #pragma unroll
        for (int i = 0; i < 4; i++) av[i] = As[ty * 4 + i][kk];
        #pragma unroll
        for (int j = 0; j < 2; j++) wv[j] = Ws[tx * 2 + j][kk];
        #pragma unroll
        for (int i = 0; i < 4; i++)
            #pragma unroll
            for (int j = 0; j < 2; j++) acc[i][j] += av[i] * wv[j];
    }
    #pragma unroll
    for (int i = 0; i < 4; i++)
        #pragma unroll
        for (int j = 0; j < 2; j++)
            atomicAdd(&C[(size_t)(ty * 4 + i) * D + e0 + tx * 2 + j], acc[i][j]);
}

// ---------------------------------------------------------------------------
// Stream launch. grid (BATCH, 290), 512 threads.
//  y in [0,257):   scores role (R13)
//  y in [257,289): attn role (R13) + attn_done bump
//  y == 289:       out-projection GEMM role (runs in the drain wave)
__global__ void __launch_bounds__(512)
stream_kernel(const float* __restrict__ prev_k, const float* __restrict__ prev_v,
              const float* __restrict__ Wo, float* __restrict__ out,
              float* __restrict__ k_out, float* __restrict__ v_out) {
    const int b = blockIdx.x;
    const int y = blockIdx.y;
    const int tid = threadIdx.x;
    const int wid = tid >> 5, lane = tid & 31;

    __shared__ union {
        float4 qs[D / 4];
        struct { float As[64][65]; float Ws[16][65]; } g;
    } sm;
    __shared__ float ps[132];

    if (y < 257) {
        // ================= scores role =================
        for (int i = tid; i < D / 4; i += 512)
            sm.qs[i] = ((const float4*)(g_q + b * D))[i];
        __syncthreads();

        int s = y * 16 + wid;
        float e = 0.f;
        if (s <= KV) {
            const float4* src = (s < KV)
                ? (const float4*)(prev_k + ((size_t)b * KV + s) * D)
                : (const float4*)(g_knew + b * D);
            float4* dst = (float4*)(k_out + ((size_t)b * KV1 + s) * D);

            float4 kv[8];
            #pragma unroll
            for (int i = 0; i < 8; i++) kv[i] = __ldcs(src + lane + i * 32);

            float acc = 0.f;
            #pragma unroll
            for (int i = 0; i < 8; i++) {
                float4 qv = sm.qs[lane + i * 32];
                acc += kv[i].x * qv.x + kv[i].y * qv.y + kv[i].z * qv.z + kv[i].w * qv.w;
                __stcs(dst + lane + i * 32, kv[i]);
            }
            #pragma unroll
            for (int o = 16; o; o >>= 1) acc += __shfl_xor_sync(0xffffffffu, acc, o);
            e = __expf(acc * 0.03125f);            // 1/sqrt(1024)
            if (lane == 0) g_scores[b * KV1 + s] = e;
        }
        if (lane == 0) ps[wid] = e;
        __syncthreads();
        if (tid < 32) {
            float v = (tid < 16) ? ps[tid] : 0.f;
            #pragma unroll
            for (int o = 16; o; o >>= 1) v += __shfl_xor_sync(0xffffffffu, v, o);
            if (tid == 0) {
                atomicAdd(&g_sumexp[b], v);
                __threadfence();
                int chunk = y >> 3; if (chunk > 31) chunk = 31;
                atomicAdd(&g_ready[b * NCHUNK + chunk], 1);
            }
        }

    } else if (y < 289) {
        // ================= attn role =================
        const int chunk = y - 257;
        const int s0 = chunk * 128;
        const bool last = (chunk == NCHUNK - 1);
        const int target = last ? 9 : 8;

        if (tid == 0) {
            while (atomicAdd(&g_ready[b * NCHUNK + chunk], 0) < target) { }
        }
        __syncthreads();
        __threadfence();

        const float* p = g_scores + b * KV1;
        if (tid < 128) ps[tid] = p[s0 + tid];
        if (last && tid == 128) ps[128] = p[KV];
        __syncthreads();

        const int col = tid & 255;
        const int rbeg = (tid >> 8) * 64;
        const float4* vbase = (const float4*)(prev_v + (size_t)b * KV * D) + col;
        float4* obase = (float4*)(v_out + (size_t)b * KV1 * D) + col;

        float4 acc = make_float4(0.f, 0.f, 0.f, 0.f);
        for (int s = 0; s < 64; s += 8) {
            float4 val[8];
            #pragma unroll
            for (int j = 0; j < 8; j++)
                val[j] = __ldcs(vbase + (size_t)(s0 + rbeg + s + j) * (D / 4));
            #pragma unroll
            for (int j = 0; j < 8; j++) {
                float w = ps[rbeg + s + j];
                acc.x += w * val[j].x; acc.y += w * val[j].y;
                acc.z += w * val[j].z; acc.w += w * val[j].w;
                __stcs(obase + (size_t)(s0 + rbeg + s + j) * (D / 4), val[j]);
            }
        }
        if (last && rbeg == 0) {                   // new row s = 4096
            float4 val = ((const float4*)(g_vnew + b * D))[col];
            float w = ps[128];
            acc.x += w * val.x; acc.y += w * val.y;
            acc.z += w * val.z; acc.w += w * val.w;
            __stcs(obase + (size_t)KV * (D / 4), val);
        }
        float* ga = g_attn + b * D + col * 4;
        atomicAdd(ga + 0, acc.x);
        atomicAdd(ga + 1, acc.y);
        atomicAdd(ga + 2, acc.z);
        atomicAdd(ga + 3, acc.w);
        __threadfence();
        __syncthreads();
        if (tid == 0) atomicAdd(&g_attn_done, 1);

    } else {
        // ================= out-projection GEMM role =================
        // 64 blocks; block b owns e-tile [b*16, b*16+16). Full K reduction.
        const int e0 = b * 16;
        const int tx = tid & 15;                   // e col
        const int ty = tid >> 4;                   // 0..31 -> 2 b-rows each

        if (tid == 0) {
            while (atomicAdd(&g_attn_done, 0) < N_AT) __nanosleep(128);
        }
        __syncthreads();
        __threadfence();

        float acc[2] = {};
        for (int k0 = 0; k0 < D; k0 += 64) {
            for (int i = tid; i < 1024; i += 512) {            // A: 64x64 floats
                int rw = i >> 4, c4 = (i & 15) * 4;
                float4 a = *(const float4*)(g_attn + (size_t)rw * D + k0 + c4);
                sm.g.As[rw][c4 + 0] = a.x; sm.g.As[rw][c4 + 1] = a.y;
                sm.g.As[rw][c4 + 2] = a.z; sm.g.As[rw][c4 + 3] = a.w;
            }
            if (tid < 256) {                                    // W: 16x64 floats
                int rw = tid >> 4, c4 = (tid & 15) * 4;
                float4 w = *(const float4*)(Wo + (size_t)(e0 + rw) * D + k0 + c4);
                sm.g.Ws[rw][c4 + 0] = w.x; sm.g.Ws[rw][c4 + 1] = w.y;
                sm.g.Ws[rw][c4 + 2] = w.z; sm.g.Ws[rw][c4 + 3] = w.w;
            }
            __syncthreads();
            #pragma unroll
            for (int kk = 0; kk < 64; kk++) {
                float w = sm.g.Ws[tx][kk];
                #pragma unroll
                for (int i = 0; i < 2; i++) acc[i] += sm.g.As[ty * 2 + i][kk] * w;
            }
            __syncthreads();
        }
        #pragma unroll
        for (int i = 0; i < 2; i++) {
            int row = ty * 2 + i;
            float scale = 1.0f / g_sumexp[row];
            float* o = &out[(size_t)row * D + e0 + tx];
            *o = *o + acc[i] * scale;              // bias preloaded; sole owner
        }
    }
}

// ---------------------------------------------------------------------------
extern "C" void kernel_launch(void* const* d_in, const int* in_sizes, int n_in,
                              void* d_out, int out_size) {
    const int*   x      = (const int*)d_in[0];
    const float* prev_k = (const float*)d_in[1];
    const float* prev_v = (const float*)d_in[2];
    const float* emb    = (const float*)d_in[3];
    const float* Wq     = (const float*)d_in[4];
    const float* bq     = (const float*)d_in[5];
    const float* Wk     = (const float*)d_in[6];
    const float* bk     = (const float*)d_in[7];
    const float* Wv     = (const float*)d_in[8];
    const float* bv     = (const float*)d_in[9];
    const float* Wo     = (const float*)d_in[10];
    const float* bo     = (const float*)d_in[11];

    float* out   = (float*)d_out;                       // (64, 1, 1024)
    float* k_out = out + (size_t)BATCH * D;             // (64, 4097, 1024)
    float* v_out = k_out + (size_t)BATCH * KV1 * D;     // (64, 4097, 1024)

    init_kernel<<<BATCH, 512>>>(x, emb, bq, bk, bv, bo, out);
    gemm_qkv<<<dim3(32, 16, 3), 256>>>(Wq, Wk, Wv);
    stream_kernel<<<dim3(BATCH, 290), 512>>>(prev_k, prev_v, Wo, out, k_out, v_out);
}

// round 16
// speedup vs baseline: 1.0086x; 1.0054x over previous
#include <cuda_runtime.h>
#include <cuda_bf16.h>

#define D      1024
#define BATCH  64
#define KV     4096
#define KV1    4097
#define NCHUNK 32
#define N_G0   1536          // QKV gemm blocks (dispatched first)
#define Y_SC   24            // scores role starts at this y
#define Y_AT   281           // attn role starts here
#define Y_ALL  313

// Scratch (no allocations allowed) ------------------------------------------
__device__ float g_cur[BATCH * D];
__device__ float g_q[BATCH * D];
__device__ float g_knew[BATCH * D];
__device__ float g_vnew[BATCH * D];
__device__ float g_scores[BATCH * KV1];   // exp(score), unnormalized
__device__ float g_attn[BATCH * D];
__device__ float g_sumexp[BATCH];
__device__ int   g_ready[BATCH * NCHUNK];
__device__ int   g_qkv_done;

// ---------------------------------------------------------------------------
__global__ void init_kernel(const int* __restrict__ x, const float* __restrict__ emb,
                            const float* __restrict__ bq, const float* __restrict__ bk,
                            const float* __restrict__ bv, const float* __restrict__ bo,
                            float* __restrict__ out) {
    int b = blockIdx.x;
    int row = x[b];
    if (threadIdx.x < NCHUNK) g_ready[b * NCHUNK + threadIdx.x] = 0;
    if (threadIdx.x == 0) {
        g_sumexp[b] = 0.f;
        if (b == 0) g_qkv_done = 0;
    }
    for (int i = threadIdx.x; i < D; i += blockDim.x) {
        g_cur[b * D + i]  = emb[(size_t)row * D + i];
        g_q[b * D + i]    = bq[i];
        g_knew[b * D + i] = bk[i];
        g_vnew[b * D + i] = bv[i];
        g_attn[b * D + i] = 0.f;
        out[b * D + i]    = bo[i];
    }
}

// ---------------------------------------------------------------------------
// Stream launch. grid (BATCH, 313), 512 threads, roles by y:
//  y <  24 : QKV GEMM blocks (id = y*64+x in [0,1536)) — no spinning.
//  y < 281 : scores role — front-issues KV loads, THEN waits for qkv_done.
//  y < 313 : attn role — identical to the R13 champion.
__global__ void __launch_bounds__(512)
stream_kernel(const float* __restrict__ prev_k, const float* __restrict__ prev_v,
              const float* __restrict__ Wq, const float* __restrict__ Wk,
              const float* __restrict__ Wv,
              float* __restrict__ k_out, float* __restrict__ v_out) {
    const int b = blockIdx.x;
    const int y = blockIdx.y;
    const int tid = threadIdx.x;
    const int wid = tid >> 5, lane = tid & 31;

    __shared__ union {
        float4 qs[D / 4];
        struct { float As[64][65]; float Ws[32][65]; } g;
    } sm;
    __shared__ float ps[132];

    if (y < Y_SC) {
        // ===================== QKV GEMM role =====================
        const int id = y * BATCH + b;            // 0..1535
        const int z  = id / 512;
        const int r  = id % 512;
        const int e0 = (r & 31) * 32;
        const int k0 = (r >> 5) * 64;
        const float* W = (z == 0) ? Wq : (z == 1) ? Wk : Wv;
        float* C = (z == 0) ? g_q : (z == 1) ? g_knew : g_vnew;

        const int ty = tid >> 5;                 // 0..15 -> 4 b-rows
        const int tx = tid & 31;                 // 0..31 -> 1 e-col

        for (int i = tid; i < 1024; i += 512) {
            int rw = i >> 4, c4 = (i & 15) * 4;
            float4 a = *(const float4*)(g_cur + (size_t)rw * D + k0 + c4);
            sm.g.As[rw][c4 + 0] = a.x; sm.g.As[rw][c4 + 1] = a.y;
            sm.g.As[rw][c4 + 2] = a.z; sm.g.As[rw][c4 + 3] = a.w;
        }
        {
            int rw = tid >> 4, c4 = (tid & 15) * 4;
            float4 w = *(const float4*)(W + (size_t)(e0 + rw) * D + k0 + c4);
            sm.g.Ws[rw][c4 + 0] = w.x; sm.g.Ws[rw][c4 + 1] = w.y;
            sm.g.Ws[rw][c4 + 2] = w.z; sm.g.Ws[rw][c4 + 3] = w.w;
        }
        __syncthreads();
        float acc[4] = {};
        #pragma unroll
        for (int kk = 0; kk < 64; kk++) {
            float w = sm.g.Ws[tx][kk];
            #pragma unroll
            for (int i = 0; i < 4; i++) acc[i] += sm.g.As[ty * 4 + i][kk] * w;
        }
        #pragma unroll
        for (int i = 0; i < 4; i++)
            atomicAdd(&C[(size_t)(ty * 4 + i) * D + e0 + tx], acc[i]);
        __threadfence();
        __syncthreads();
        if (tid == 0) atomicAdd(&g_qkv_done, 1);

    } else if (y < Y_AT) {
        // ===================== scores role =====================
        const int sy = y - Y_SC;                 // 0..256
        const int s = sy * 16 + wid;
        const bool valid = (s <= KV);
        const bool from_prev = (s < KV);

        // Front-issue the 8 KV cache loads BEFORE waiting (prev_k only).
        float4 kv[8];
        if (from_prev) {
            const float4* src = (const float4*)(prev_k + ((size_t)b * KV + s) * D);
            #pragma unroll
            for (int i = 0; i < 8; i++) kv[i] = __ldcs(src + lane + i * 32);
        }

        if (tid == 0) {
            while (atomicAdd(&g_qkv_done, 0) < N_G0) { }
        }
        __syncthreads();
        __threadfence();

        for (int i = tid; i < D / 4; i += 512)
            sm.qs[i] = ((const float4*)(g_q + b * D))[i];
        __syncthreads();

        float e = 0.f;
        if (valid) {
            if (!from_prev) {                    // s == KV: k_new row (post-flag)
                const float4* src = (const float4*)(g_knew + b * D);
                #pragma unroll
                for (int i = 0; i < 8; i++) kv[i] = src[lane + i * 32];
            }
            float4* dst = (float4*)(k_out + ((size_t)b * KV1 + s) * D);
            float acc = 0.f;
            #pragma unroll
            for (int i = 0; i < 8; i++) {
                float4 qv = sm.qs[lane + i * 32];
                acc += kv[i].x * qv.x + kv[i].y * qv.y + kv[i].z * qv.z + kv[i].w * qv.w;
                __stcs(dst + lane + i * 32, kv[i]);
            }
            #pragma unroll
            for (int o = 16; o; o >>= 1) acc += __shfl_xor_sync(0xffffffffu, acc, o);
            e = __expf(acc * 0.03125f);          // 1/sqrt(1024)
            if (lane == 0) g_scores[b * KV1 + s] = e;
        }
        if (lane == 0) ps[wid] = e;
        __syncthreads();
        if (tid < 32) {
            float v = (tid < 16) ? ps[tid] : 0.f;
            #pragma unroll
            for (int o = 16; o; o >>= 1) v += __shfl_xor_sync(0xffffffffu, v, o);
            if (tid == 0) {
                atomicAdd(&g_sumexp[b], v);
                __threadfence();
                int chunk = sy >> 3; if (chunk > 31) chunk = 31;
                atomicAdd(&g_ready[b * NCHUNK + chunk], 1);
            }
        }

    } else {
        // ===================== attn role (exact R13) =====================
        const int chunk = y - Y_AT;
        const int s0 = chunk * 128;
        const bool last = (chunk == NCHUNK - 1);
        const int target = last ? 9 : 8;

        if (tid == 0) {
            while (atomicAdd(&g_ready[b * NCHUNK + chunk], 0) < target) { }
        }
        __syncthreads();
        __threadfence();

        const float* p = g_scores + b * KV1;
        if (tid < 128) ps[tid] = p[s0 + tid];
        if (last && tid == 128) ps[128] = p[KV];
        __syncthreads();

        const int col = tid & 255;
        const int rbeg = (tid >> 8) * 64;
        const float4* vbase = (const float4*)(prev_v + (size_t)b * KV * D) + col;
        float4* obase = (float4*)(v_out + (size_t)b * KV1 * D) + col;

        float4 acc = make_float4(0.f, 0.f, 0.f, 0.f);
        for (int s = 0; s < 64; s += 8) {
            float4 val[8];
            #pragma unroll
            for (int j = 0; j < 8; j++)
                val[j] = __ldcs(vbase + (size_t)(s0 + rbeg + s + j) * (D / 4));
            #pragma unroll
            for (int j = 0; j < 8; j++) {
                float w = ps[rbeg + s + j];
                acc.x += w * val[j].x; acc.y += w * val[j].y;
                acc.z += w * val[j].z; acc.w += w * val[j].w;
                __stcs(obase + (size_t)(s0 + rbeg + s + j) * (D / 4), val[j]);
            }
        }
        if (last && rbeg == 0) {                 // new row s = 4096
            float4 val = ((const float4*)(g_vnew + b * D))[col];
            float w = ps[128];
            acc.x += w * val.x; acc.y += w * val.y;
            acc.z += w * val.z; acc.w += w * val.w;
            __stcs(obase + (size_t)KV * (D / 4), val);
        }
        float* ga = g_attn + b * D + col * 4;
        atomicAdd(ga + 0, acc.x);
        atomicAdd(ga + 1, acc.y);
        atomicAdd(ga + 2, acc.z);
        atomicAdd(ga + 3, acc.w);
    }
}

// ---------------------------------------------------------------------------
// Out-projection split-K GEMM (champion R13 mode-1): grid (32,16), 256 threads.
__global__ void gemm_out(const float* __restrict__ Wo, float* __restrict__ Cext) {
    __shared__ float As[64][65];
    __shared__ float Ws[32][65];
    const int e0 = blockIdx.x * 32;
    const int k0 = blockIdx.y * 64;
    const int tid = threadIdx.x;
    const int ty = tid >> 4, tx = tid & 15;
    float acc[4][2] = {};

    for (int i = tid; i < 1024; i += 256) {
        int row = i >> 4, c4 = (i & 15) * 4;
        float4 a = *(const float4*)(g_attn + (size_t)row * D + k0 + c4);
        As[row][c4 + 0] = a.x; As[row][c4 + 1] = a.y;
        As[row][c4 + 2] = a.z; As[row][c4 + 3] = a.w;
    }
    for (int i = tid; i < 512; i += 256) {
        int row = i >> 4, c4 = (i & 15) * 4;
        float4 w = *(const float4*)(Wo + (size_t)(e0 + row) * D + k0 + c4);
        Ws[row][c4 + 0] = w.x; Ws[row][c4 + 1] = w.y;
        Ws[row][c4 + 2] = w.z; Ws[row][c4 + 3] = w.w;
    }
    __syncthreads();
    #pragma unroll
    for (int kk = 0; kk < 64; kk++) {
        float av[4], wv[2];
        #pragma unroll
        for (int i = 0; i < 4; i++) av[i] = As[ty * 4 + i][kk];
        #pragma unroll
        for (int j = 0; j < 2; j++) wv[j] = Ws[tx * 2 + j][kk];
        #pragma unroll
        for (int i = 0; i < 4; i++)
            #pragma unroll
            for (int j = 0; j < 2; j++) acc[i][j] += av[i] * wv[j];
    }
    #pragma unroll
    for (int i = 0; i < 4; i++) {
        int b = ty * 4 + i;
        float scale = 1.0f / g_sumexp[b];
        #pragma unroll
        for (int j = 0; j < 2; j++)
            atomicAdd(&Cext[(size_t)b * D + e0 + tx * 2 + j], acc[i][j] * scale);
    }
}

// ---------------------------------------------------------------------------
extern "C" void kernel_launch(void* const* d_in, const int* in_sizes, int n_in,
                              void* d_out, int out_size) {
    const int*   x      = (const int*)d_in[0];
    const float* prev_k = (const float*)d_in[1];
    const float* prev_v = (const float*)d_in[2];
    const float* emb    = (const float*)d_in[3];
    const float* Wq     = (const float*)d_in[4];
    const float* bq     = (const float*)d_in[5];
    const float* Wk     = (const float*)d_in[6];
    const float* bk     = (const float*)d_in[7];
    const float* Wv     = (const float*)d_in[8];
    const float* bv     = (const float*)d_in[9];
    const float* Wo     = (const float*)d_in[10];
    const float* bo     = (const float*)d_in[11];

    float* out   = (float*)d_out;                       // (64, 1, 1024)
    float* k_out = out + (size_t)BATCH * D;             // (64, 4097, 1024)
    float* v_out = k_out + (size_t)BATCH * KV1 * D;     // (64, 4097, 1024)

    init_kernel<<<BATCH, 512>>>(x, emb, bq, bk, bv, bo, out);
    stream_kernel<<<dim3(BATCH, Y_ALL), 512>>>(prev_k, prev_v, Wq, Wk, Wv,
                                               k_out, v_out);
    gemm_out<<<dim3(32, 16), 256>>>(Wo, out);
}

// round 17
// speedup vs baseline: 1.0621x; 1.0530x over previous
#include <cuda_runtime.h>
#include <cuda_bf16.h>

#define D      1024
#define BATCH  64
#define KV     4096
#define KV1    4097
#define NCHUNK 32

// Scratch (no allocations allowed) ------------------------------------------
__device__ float g_q[BATCH * D];
__device__ float g_knew[BATCH * D];
__device__ float g_vnew[BATCH * D];
__device__ float g_scores[BATCH * KV1];   // exp(score), unnormalized
__device__ float g_attn[BATCH * D];
__device__ float g_sumexp[BATCH];
__device__ int   g_ready[BATCH * NCHUNK];

// ---------------------------------------------------------------------------
// Launch 1: bias pre-init + flag zeroing. grid (BATCH, 4), 256 threads.
__global__ void init_kernel(const float* __restrict__ bq, const float* __restrict__ bk,
                            const float* __restrict__ bv, const float* __restrict__ bo,
                            float* __restrict__ out) {
    int b = blockIdx.x;
    int i = blockIdx.y * 256 + threadIdx.x;
    if (blockIdx.y == 0) {
        if (threadIdx.x < NCHUNK) g_ready[b * NCHUNK + threadIdx.x] = 0;
        if (threadIdx.x == 0) g_sumexp[b] = 0.f;
    }
    g_q[b * D + i]    = bq[i];
    g_knew[b * D + i] = bk[i];
    g_vnew[b * D + i] = bv[i];
    g_attn[b * D + i] = 0.f;
    out[b * D + i]    = bo[i];
}

// ---------------------------------------------------------------------------
// Launch 2: QKV split-K GEMM, A gathered straight from emb via x.
// grid (32,16,3), 256 threads.  C[b,e] += sum_{k in 64-slice} emb[x[b],k]*W[e,k]
__global__ void gemm_qkv(const int* __restrict__ x, const float* __restrict__ emb,
                         const float* __restrict__ Wq, const float* __restrict__ Wk,
                         const float* __restrict__ Wv) {
    const float* W = (blockIdx.z == 0) ? Wq : (blockIdx.z == 1) ? Wk : Wv;
    float* C = (blockIdx.z == 0) ? g_q : (blockIdx.z == 1) ? g_knew : g_vnew;

    __shared__ float As[64][65];
    __shared__ float Ws[32][65];
    __shared__ int   xs[64];
    const int e0 = blockIdx.x * 32;
    const int k0 = blockIdx.y * 64;
    const int tid = threadIdx.x;
    const int ty = tid >> 4, tx = tid & 15;
    float acc[4][2] = {};

    if (tid < 64) xs[tid] = x[tid];
    __syncthreads();

    for (int i = tid; i < 1024; i += 256) {
        int row = i >> 4, c4 = (i & 15) * 4;
        float4 a = *(const float4*)(emb + (size_t)xs[row] * D + k0 + c4);
        As[row][c4 + 0] = a.x; As[row][c4 + 1] = a.y;
        As[row][c4 + 2] = a.z; As[row][c4 + 3] = a.w;
    }
    for (int i = tid; i < 512; i += 256) {
        int row = i >> 4, c4 = (i & 15) * 4;
        float4 w = *(const float4*)(W + (size_t)(e0 + row) * D + k0 + c4);
        Ws[row][c4 + 0] = w.x; Ws[row][c4 + 1] = w.y;
        Ws[row][c4 + 2] = w.z; Ws[row][c4 + 3] = w.w;
    }
    __syncthreads();
    #pragma unroll
    for (int kk = 0; kk < 64; kk++) {
        float av[4], wv[2];
        #pragma unroll
        for (int i = 0; i < 4; i++) av[i] = As[ty * 4 + i][kk];
        #pragma unroll
        for (int j = 0; j < 2; j++) wv[j] = Ws[tx * 2 + j][kk];
        #pragma unroll
        for (int i = 0; i < 4; i++)
            #pragma unroll
            for (int j = 0; j < 2; j++) acc[i][j] += av[i] * wv[j];
    }
    #pragma unroll
    for (int i = 0; i < 4; i++)
        #pragma unroll
        for (int j = 0; j < 2; j++)
            atomicAdd(&C[(size_t)(ty * 4 + i) * D + e0 + tx * 2 + j], acc[i][j]);
}

// ---------------------------------------------------------------------------
// Launch 3 (champion R13): pipelined scores->attn stream. grid (BATCH, 289).
__global__ void stream_kernel(const float* __restrict__ prev_k,
                              const float* __restrict__ prev_v,
                              float* __restrict__ k_out,
                              float* __restrict__ v_out) {
    const int b = blockIdx.x;
    const int y = blockIdx.y;
    const int tid = threadIdx.x;
    const int wid = tid >> 5, lane = tid & 31;

    __shared__ float4 qs[D / 4];
    __shared__ float ps[132];

    if (y < 257) {
        // ================= scores role =================
        for (int i = tid; i < D / 4; i += 512)
            qs[i] = ((const float4*)(g_q + b * D))[i];
        __syncthreads();

        int s = y * 16 + wid;
        float e = 0.f;
        if (s <= KV) {
            const float4* src = (s < KV)
                ? (const float4*)(prev_k + ((size_t)b * KV + s) * D)
                : (const float4*)(g_knew + b * D);
            float4* dst = (float4*)(k_out + ((size_t)b * KV1 + s) * D);

            float4 kv[8];
            #pragma unroll
            for (int i = 0; i < 8; i++) kv[i] = __ldcs(src + lane + i * 32);

            float acc = 0.f;
            #pragma unroll
            for (int i = 0; i < 8; i++) {
                float4 qv = qs[lane + i * 32];
                acc += kv[i].x * qv.x + kv[i].y * qv.y + kv[i].z * qv.z + kv[i].w * qv.w;
                __stcs(dst + lane + i * 32, kv[i]);
            }
            #pragma unroll
            for (int o = 16; o; o >>= 1) acc += __shfl_xor_sync(0xffffffffu, acc, o);
            e = __expf(acc * 0.03125f);            // 1/sqrt(1024)
            if (lane == 0) g_scores[b * KV1 + s] = e;
        }
        if (lane == 0) ps[wid] = e;
        __syncthreads();
        if (tid < 32) {
            float v = (tid < 16) ? ps[tid] : 0.f;
            #pragma unroll
            for (int o = 16; o; o >>= 1) v += __shfl_xor_sync(0xffffffffu, v, o);
            if (tid == 0) {
                atomicAdd(&g_sumexp[b], v);
                __threadfence();
                int chunk = y >> 3; if (chunk > 31) chunk = 31;
                atomicAdd(&g_ready[b * NCHUNK + chunk], 1);
            }
        }
    } else {
        // ================= attn role =================
        const int chunk = y - 257;
        const int s0 = chunk * 128;
        const bool last = (chunk == NCHUNK - 1);
        const int target = last ? 9 : 8;

        if (tid == 0) {
            while (atomicAdd(&g_ready[b * NCHUNK + chunk], 0) < target) { }
        }
        __syncthreads();
        __threadfence();

        const float* p = g_scores + b * KV1;
        if (tid < 128) ps[tid] = p[s0 + tid];
        if (last && tid == 128) ps[128] = p[KV];
        __syncthreads();

        const int col = tid & 255;
        const int rbeg = (tid >> 8) * 64;
        const float4* vbase = (const float4*)(prev_v + (size_t)b * KV * D) + col;
        float4* obase = (float4*)(v_out + (size_t)b * KV1 * D) + col;

        float4 acc = make_float4(0.f, 0.f, 0.f, 0.f);
        for (int s = 0; s < 64; s += 8) {
            float4 val[8];
            #pragma unroll
            for (int j = 0; j < 8; j++)
                val[j] = __ldcs(vbase + (size_t)(s0 + rbeg + s + j) * (D / 4));
            #pragma unroll
            for (int j = 0; j < 8; j++) {
                float w = ps[rbeg + s + j];
                acc.x += w * val[j].x; acc.y += w * val[j].y;
                acc.z += w * val[j].z; acc.w += w * val[j].w;
                __stcs(obase + (size_t)(s0 + rbeg + s + j) * (D / 4), val[j]);
            }
        }
        if (last && rbeg == 0) {                   // new row s = 4096
            float4 val = ((const float4*)(g_vnew + b * D))[col];
            float w = ps[128];
            acc.x += w * val.x; acc.y += w * val.y;
            acc.z += w * val.z; acc.w += w * val.w;
            __stcs(obase + (size_t)KV * (D / 4), val);
        }
        float* ga = g_attn + b * D + col * 4;
        atomicAdd(ga + 0, acc.x);
        atomicAdd(ga + 1, acc.y);
        atomicAdd(ga + 2, acc.z);
        atomicAdd(ga + 3, acc.w);
    }
}

// ---------------------------------------------------------------------------
// Launch 4 (champion R13): out-projection split-K GEMM. grid (32,16), 256 thr.
__global__ void gemm_out(const float* __restrict__ Wo, float* __restrict__ Cext) {
    __shared__ float As[64][65];
    __shared__ float Ws[32][65];
    const int e0 = blockIdx.x * 32;
    const int k0 = blockIdx.y * 64;
    const int tid = threadIdx.x;
    const int ty = tid >> 4, tx = tid & 15;
    float acc[4][2] = {};

    for (int i = tid; i < 1024; i += 256) {
        int row = i >> 4, c4 = (i & 15) * 4;
        float4 a = *(const float4*)(g_attn + (size_t)row * D + k0 + c4);
        As[row][c4 + 0] = a.x; As[row][c4 + 1] = a.y;
        As[row][c4 + 2] = a.z; As[row][c4 + 3] = a.w;
    }
    for (int i = tid; i < 512; i += 256) {
        int row = i >> 4, c4 = (i & 15) * 4;
        float4 w = *(const float4*)(Wo + (size_t)(e0 + row) * D + k0 + c4);
        Ws[row][c4 + 0] = w.x; Ws[row][c4 + 1] = w.y;
        Ws[row][c4 + 2] = w.z; Ws[row][c4 + 3] = w.w;
    }
    __syncthreads();
    #pragma unroll
    for (int kk = 0; kk < 64; kk++) {
        float av[4], wv[2];
        #pragma unroll
        for (int i = 0; i < 4; i++) av[i] = As[ty * 4 + i][kk];
        #pragma unroll
        for (int j = 0; j < 2; j++) wv[j] = Ws[tx * 2 + j][kk];
        #pragma unroll
        for (int i = 0; i < 4; i++)
            #pragma unroll
            for (int j = 0; j < 2; j++) acc[i][j] += av[i] * wv[j];
    }
    #pragma unroll
    for (int i = 0; i < 4; i++) {
        int b = ty * 4 + i;
        float scale = 1.0f / g_sumexp[b];
        #pragma unroll
        for (int j = 0; j < 2; j++)
            atomicAdd(&Cext[(size_t)b * D + e0 + tx * 2 + j], acc[i][j] * scale);
    }
}

// ---------------------------------------------------------------------------
extern "C" void kernel_launch(void* const* d_in, const int* in_sizes, int n_in,
                              void* d_out, int out_size) {
    const int*   x      = (const int*)d_in[0];
    const float* prev_k = (const float*)d_in[1];
    const float* prev_v = (const float*)d_in[2];
    const float* emb    = (const float*)d_in[3];
    const float* Wq     = (const float*)d_in[4];
    const float* bq     = (const float*)d_in[5];
    const float* Wk     = (const float*)d_in[6];
    const float* bk     = (const float*)d_in[7];
    const float* Wv     = (const float*)d_in[8];
    const float* bv     = (const float*)d_in[9];
    const float* Wo     = (const float*)d_in[10];
    const float* bo     = (const float*)d_in[11];

    float* out   = (float*)d_out;                       // (64, 1, 1024)
    float* k_out = out + (size_t)BATCH * D;             // (64, 4097, 1024)
    float* v_out = k_out + (size_t)BATCH * KV1 * D;     // (64, 4097, 1024)

    init_kernel<<<dim3(BATCH, 4), 256>>>(bq, bk, bv, bo, out);
    gemm_qkv<<<dim3(32, 16, 3), 256>>>(x, emb, Wq, Wk, Wv);
    stream_kernel<<<dim3(BATCH, 289), 512>>>(prev_k, prev_v, k_out, v_out);
    gemm_out<<<dim3(32, 16), 256>>>(Wo, out);
}